// round 12
// baseline (speedup 1.0000x reference)
#include <cuda_runtime.h>
#include <math.h>

#define EPSF 1e-8f
typedef unsigned long long u64;

struct F3 { float x, y, z; };

__device__ __forceinline__ F3 f3sub(F3 a, F3 b) { return {a.x - b.x, a.y - b.y, a.z - b.z}; }
__device__ __forceinline__ F3 f3cross(F3 a, F3 b) {
    return {a.y * b.z - a.z * b.y,
            a.z * b.x - a.x * b.z,
            a.x * b.y - a.y * b.x};
}
__device__ __forceinline__ float f3dot(F3 a, F3 b) { return a.x * b.x + a.y * b.y + a.z * b.z; }

// ---- packed f32x2 helpers (sm_103a FFMA2; PTX-only, ptxas never auto-fuses) ----
__device__ __forceinline__ u64 pack2(float a, float b) {
    u64 r; asm("mov.b64 %0, {%1, %2};" : "=l"(r) : "f"(a), "f"(b)); return r;
}
__device__ __forceinline__ u64 ffma2(u64 a, u64 b, u64 c) {
    u64 d; asm("fma.rn.f32x2 %0, %1, %2, %3;" : "=l"(d) : "l"(a), "l"(b), "l"(c)); return d;
}

// sin/cos of (acos(c) * sign): sin = sign*sqrt(1-c^2), cos = (sign!=0 ? c : 1).
__device__ __forceinline__ void angle_sc(float num, float f1, float f2, float sg,
                                         float& s_out, float& c_out) {
    float inv = __fdividef(1.0f, f1 * f2);
    float c = num * inv;
    c = fminf(1.0f, fmaxf(-1.0f, c));
    float sinmag = sqrtf(fmaxf(fmaf(-c, c, 1.0f), 0.0f));
    s_out = (sg > 0.0f) ? sinmag : ((sg < 0.0f) ? -sinmag : 0.0f);
    c_out = (sg != 0.0f) ? c : 1.0f;
}

static constexpr int Lc  = 4096;   // sequence length (power of 2, TPB divides it)
static constexpr int Dc  = 64;     // output features
static constexpr int TPB = 128;

__global__ void __launch_bounds__(TPB, 10)
dihedral_encoder_kernel(const float* __restrict__ coords,
                        const float* __restrict__ W,      // (64, 6) row-major
                        const float* __restrict__ bias,   // (64,)
                        float* __restrict__ out,          // (B*L, 64)
                        int total)
{
    // Staged coords: rows g0-1 .. g0+TPB (halo), 12 floats per row.
    __shared__ __align__(16) float4 sC4[(TPB + 2) * 3];
    __shared__ __align__(16) float sW[6 * Dc];   // transposed: sW[j*64+d] = W[d][j]
    __shared__ __align__(16) float sB[Dc];
    // Encoded e-pairs: 6 u64 per residue, 48B row stride (word stride 12 ->
    // gcd(12,32)=4 => only 4-way bank conflicts, vs 16-way at 64B stride).
    __shared__ __align__(16) u64 sEd[TPB * 6];

    int t = threadIdx.x;
    int g0 = blockIdx.x * TPB;

    // ---- Stage coords (fully coalesced float4 loads, clamped halo) ----
    {
        const float4* c4 = reinterpret_cast<const float4*>(coords);
        long maxI = (long)total * 3 - 1;
        long base = (long)g0 * 3 - 3;            // first float4 of halo row g0-1
        #pragma unroll
        for (int k = t; k < (TPB + 2) * 3; k += TPB) {
            long gi = base + k;
            gi = gi < 0 ? 0 : (gi > maxI ? maxI : gi);   // clamped rows are never consumed
            sC4[k] = c4[gi];
        }
    }
    if (t < Dc) {
        sB[t] = bias[t];
        #pragma unroll
        for (int j = 0; j < 6; j++) sW[j * Dc + t] = W[t * 6 + j];
    }
    __syncthreads();

    int g = g0 + t;
    bool allin = (g0 + TPB) <= total;

    // ---------------- Phase A: chained dihedral math ----------------
    {
        float e[6];
        if (allin || g < total) {
            int l = g & (Lc - 1);
            const float* sC = reinterpret_cast<const float*>(sC4);
            int lr = t + 1;                       // local row (halo at 0)
            int fb = lr * 12;

            float4 m0 = sC4[lr * 3 + 0];          // N.xyz, CA.x
            float4 m1 = sC4[lr * 3 + 1];          // CA.yz, C.xy
            float  cz = sC[fb + 8];               // C.z
            F3 N  = {m0.x, m0.y, m0.z};
            F3 CA = {m0.w, m1.x, m1.y};
            F3 C  = {m1.z, m1.w, cz};

            bool first = (l == 0);
            bool last  = (l == Lc - 1);

            // C_prev (row lr-1, floats 6..8) -> floats fb-6..fb-4 (8B aligned)
            float2 cp01 = *reinterpret_cast<const float2*>(&sC[fb - 6]);
            float  cp2  = sC[fb - 4];
            F3 Cp = first ? C : F3{cp01.x, cp01.y, cp2};

            // next row: N_next (12..14), CA_next (15..17)
            float4 n0 = sC4[lr * 3 + 3];
            float2 n1 = *reinterpret_cast<const float2*>(&sC[fb + 16]);
            F3 Nn  = last ? N : F3{n0.x, n0.y, n0.z};
            F3 CAn = {n0.w, n1.x, n1.y};          // unused (overridden) when last

            // Chained bond vectors / normals:
            //   phi  : n1=c1, n2=c2, v3=b2
            //   psi  : n1=c2, n2=c3, v3=b3
            //   omega: n1=c3, n2=c4, v3=b4   (exact (0,1) override at l==Lc-1)
            F3 b0 = f3sub(N,  Cp);
            F3 b1 = f3sub(CA, N);
            F3 b2 = f3sub(C,  CA);
            F3 b3 = f3sub(Nn, C);
            F3 b4 = f3sub(CAn, Nn);
            F3 c1 = f3cross(b0, b1);
            F3 c2 = f3cross(b1, b2);
            F3 c3 = f3cross(b2, b3);
            F3 c4 = f3cross(b3, b4);

            float s1 = f3dot(c1, c1), s2 = f3dot(c2, c2);
            float s3 = f3dot(c3, c3), s4 = f3dot(c4, c4);
            float f1 = ((s1 > 0.0f) ? sqrtf(s1) : 0.0f) + EPSF;   // _safe_norm + EPS
            float f2 = ((s2 > 0.0f) ? sqrtf(s2) : 0.0f) + EPSF;
            float f3 = ((s3 > 0.0f) ? sqrtf(s3) : 0.0f) + EPSF;
            float f4 = ((s4 > 0.0f) ? sqrtf(s4) : 0.0f) + EPSF;

            angle_sc(f3dot(c1, c2), f1, f2, f3dot(c1, b2), e[0], e[3]);  // phi
            angle_sc(f3dot(c2, c3), f2, f3, f3dot(c2, b3), e[1], e[4]);  // psi
            angle_sc(f3dot(c3, c4), f3, f4, f3dot(c3, b4), e[2], e[5]);  // omega
            if (last) { e[2] = 0.0f; e[5] = 1.0f; }   // p3==p4 => v3=0 => sign=0
        } else {
            #pragma unroll
            for (int j = 0; j < 6; j++) e[j] = 0.0f;
        }

        ulonglong2* rowp = reinterpret_cast<ulonglong2*>(&sEd[t * 6]);
        ulonglong2 q0; q0.x = pack2(e[0], e[0]); q0.y = pack2(e[1], e[1]);
        ulonglong2 q1; q1.x = pack2(e[2], e[2]); q1.y = pack2(e[3], e[3]);
        ulonglong2 q2; q2.x = pack2(e[4], e[4]); q2.y = pack2(e[5], e[5]);
        rowp[0] = q0; rowp[1] = q1; rowp[2] = q2;
    }
    __syncthreads();

    // ---------------- Phase B: coalesced packed matvec + store ----------------
    int chunk  = t & 15;
    int subrow = t >> 4;                          // 0..7

    const float4* w4 = reinterpret_cast<const float4*>(sW);
    u64 wp[6][2];
    #pragma unroll
    for (int j = 0; j < 6; j++) {
        float4 w = w4[j * 16 + chunk];
        wp[j][0] = pack2(w.x, w.y);
        wp[j][1] = pack2(w.z, w.w);
    }
    float4 bb = reinterpret_cast<const float4*>(sB)[chunk];
    u64 bp0 = pack2(bb.x, bb.y);
    u64 bp1 = pack2(bb.z, bb.w);

    ulonglong2* outBase = reinterpret_cast<ulonglong2*>(out + (size_t)g0 * Dc);
    const ulonglong2* e2 = reinterpret_cast<const ulonglong2*>(sEd);

    #pragma unroll
    for (int it = 0; it < 16; it++) {
        int row = it * 8 + subrow;                // 0..127
        if (allin || (g0 + row < total)) {
            ulonglong2 q0 = e2[row * 3 + 0];      // (e0,e0),(e1,e1)
            ulonglong2 q1 = e2[row * 3 + 1];      // (e2,e2),(e3,e3)
            ulonglong2 q2 = e2[row * 3 + 2];      // (e4,e4),(e5,e5)
            u64 a0 = bp0, a1 = bp1;
            a0 = ffma2(q0.x, wp[0][0], a0);  a1 = ffma2(q0.x, wp[0][1], a1);
            a0 = ffma2(q0.y, wp[1][0], a0);  a1 = ffma2(q0.y, wp[1][1], a1);
            a0 = ffma2(q1.x, wp[2][0], a0);  a1 = ffma2(q1.x, wp[2][1], a1);
            a0 = ffma2(q1.y, wp[3][0], a0);  a1 = ffma2(q1.y, wp[3][1], a1);
            a0 = ffma2(q2.x, wp[4][0], a0);  a1 = ffma2(q2.x, wp[4][1], a1);
            a0 = ffma2(q2.y, wp[5][0], a0);  a1 = ffma2(q2.y, wp[5][1], a1);
            ulonglong2 r; r.x = a0; r.y = a1;
            outBase[row * 16 + chunk] = r;        // warp covers 2x256B contiguous
        }
    }
}

extern "C" void kernel_launch(void* const* d_in, const int* in_sizes, int n_in,
                              void* d_out, int out_size) {
    const float* coords = (const float*)d_in[0];   // (B, L, 4, 3) f32
    const float* W      = (const float*)d_in[1];   // (64, 6) f32
    const float* bias   = (const float*)d_in[2];   // (64,) f32
    float* out          = (float*)d_out;           // (B, L, 64) f32

    int total = in_sizes[0] / 12;                  // B*L residues
    int grid = (total + TPB - 1) / TPB;
    dihedral_encoder_kernel<<<grid, TPB>>>(coords, W, bias, out, total);
}